// round 10
// baseline (speedup 1.0000x reference)
#include <cuda_runtime.h>
#include <cuda_fp16.h>
#include <math.h>
#include <stdint.h>

#define BB 32
#define VV 16
#define LL 64
#define PP 64
#define DD 64
#define NTOK 32768      // BB*VV*LL
#define NQ 8
#define BINS 1024
#define EPSF 1e-5f
#define TPAD 66

#define ZQ_OFF   (NTOK*DD)           // 2097152
#define CODES_N  (NQ*NTOK)           // 262144

typedef unsigned long long ull;

// m16n8k16 f16 mma, fp32 accum (sm_80+; legal under compute_100)
__device__ __forceinline__ void mma_f16(float* c, const uint32_t* a,
                                        uint32_t b0, uint32_t b1) {
    asm volatile("mma.sync.aligned.m16n8k16.row.col.f32.f16.f16.f32 "
        "{%0,%1,%2,%3}, {%4,%5,%6,%7}, {%8,%9}, {%0,%1,%2,%3};"
        : "+f"(c[0]), "+f"(c[1]), "+f"(c[2]), "+f"(c[3])
        : "r"(a[0]), "r"(a[1]), "r"(a[2]), "r"(a[3]), "r"(b0), "r"(b1));
}

__device__ __forceinline__ uint32_t pack_h2(float x, float y) {
    __half2 h = __floats2half2_rn(x, y);
    return *reinterpret_cast<uint32_t*>(&h);
}

// fp32x2 helpers for k_enc (lowered to 2x FFMA on sm_100; harmless)
__device__ __forceinline__ void fma2(ull& acc, ull a, ull b) {
    asm("fma.rn.f32x2 %0, %1, %2, %0;" : "+l"(acc) : "l"(a), "l"(b));
}
__device__ __forceinline__ float unpack_sum(ull a) {
    float2 p = *reinterpret_cast<float2*>(&a);
    return p.x + p.y;
}

// ---------------- scratch (device globals; no allocation allowed) -------------
__device__ __align__(16) float  g_z[NTOK*DD];
__device__ __align__(16) float  g_zh[NTOK*DD];
// fp16 HI-only fragment codebook: F = (((q*16+ch)*8+nt)*4+s)*32+lane -> {bhi0,bhi1}
__device__ __align__(16) uint2  g_cbf16h[NQ*16*8*4*32];
__device__ float  g_cbsq[NQ*BINS];
__device__ int    g_cbnmax_i[NQ];      // per-q max ||c||^2 (float bits, positive)
__device__ double g_sum[LL], g_sumsq[LL];
__device__ float  g_mean[LL], g_sinv[LL], g_spe[LL];
__device__ double g_colnorm[BB*DD];
__device__ float  g_invnorm[BB*DD];
__device__ double g_loss[NQ];

// ---------------- k0: zero accumulators ---------------------------------------
__global__ void k_zero() {
    int t = threadIdx.x;
    if (t < LL) { g_sum[t] = 0.0; g_sumsq[t] = 0.0; }
    if (t < NQ) { g_loss[t] = 0.0; g_cbnmax_i[t] = 0; }
    for (int i = t; i < BB*DD; i += blockDim.x) g_colnorm[i] = 0.0;
}

// ---------------- k1: 64-pt DFT magnitude per patch ---------------------------
__global__ void __launch_bounds__(1024) k_fft(const float* __restrict__ x) {
    __shared__ float xs[PP*VV];
    __shared__ float ct[64], st[64];
    int bi = blockIdx.x;
    int b = bi >> 6, l = bi & 63;
    int tid = threadIdx.x;
    xs[tid] = x[(size_t)(b*4096 + l*64)*16 + tid];
    if (tid < 64) { float a = (float)tid * (1.0f/32.0f); ct[tid] = cospif(a); st[tid] = sinpif(a); }
    __syncthreads();
    int v = tid >> 6, k = tid & 63;
    float re = 0.f, im = 0.f;
    #pragma unroll 16
    for (int j = 0; j < 64; j++) {
        float val = xs[j*16 + v];
        int a = (j*k) & 63;
        re += val * ct[a];
        im += val * st[a];
    }
    float mag = sqrtf(re*re + im*im);
    int t = (b*VV + v)*LL + l;
    g_z[t*64 + k] = mag;
}

// ---------------- k2: per-l sum / sumsq ----------------------------------------
__global__ void k_stats() {
    int bv = blockIdx.x;
    const float* p = g_z + bv*4096;
    int tid = threadIdx.x;
    int l = tid >> 2, seg = (tid & 3)*16;
    const float* q = p + l*64 + seg;
    float s = 0.f, ss = 0.f;
    #pragma unroll
    for (int i = 0; i < 16; i++) { float v = q[i]; s += v; ss += v*v; }
    s  += __shfl_xor_sync(0xffffffffu, s, 1);  ss += __shfl_xor_sync(0xffffffffu, ss, 1);
    s  += __shfl_xor_sync(0xffffffffu, s, 2);  ss += __shfl_xor_sync(0xffffffffu, ss, 2);
    if ((tid & 3) == 0) {
        atomicAdd(&g_sum[l], (double)s);
        atomicAdd(&g_sumsq[l], (double)ss);
    }
}

// ---------------- k3: finalize mean / std (ddof=1) ----------------------------
__global__ void k_statfin() {
    int l = threadIdx.x;
    if (l >= LL) return;
    double n = 32768.0;
    double s = g_sum[l], ss = g_sumsq[l];
    double mean = s / n;
    double var = (ss - s*s/n) / (n - 1.0);
    float sd = (float)sqrt(var);
    g_mean[l] = (float)mean;
    float spe = sd + EPSF;
    g_spe[l] = spe;
    g_sinv[l] = 1.0f / spe;
}

// ---------------- k4: codebook squared norms + per-q max ----------------------
__global__ void k_cbsq(const float* __restrict__ cb) {
    int tid = threadIdx.x;
    int row = blockIdx.x*64 + (tid >> 2);
    const float* p = cb + row*64 + (tid & 3)*16;
    float s = 0.f;
    #pragma unroll
    for (int i = 0; i < 16; i++) { float v = p[i]; s += v*v; }
    s += __shfl_xor_sync(0xffffffffu, s, 1);
    s += __shfl_xor_sync(0xffffffffu, s, 2);
    if ((tid & 3) == 0) {
        g_cbsq[row] = s;
        atomicMax(&g_cbnmax_i[row >> 10], __float_as_int(s));  // s > 0
    }
}

// ---------------- k4b: codebook -> fp16 HI mma fragments -----------------------
__global__ void k_cbfrag(const float* __restrict__ cb) {
    int F = blockIdx.x*256 + threadIdx.x;
    if (F >= NQ*16*8*4*32) return;
    int lane = F & 31;
    int s    = (F >> 5) & 3;
    int nt   = (F >> 7) & 7;
    int ch   = (F >> 10) & 15;
    int q    = F >> 14;
    int g    = lane >> 2, tig = lane & 3;
    int entry = ch*64 + nt*8 + g;
    int k0 = 16*s + 2*tig;
    const float* src = cb + ((size_t)q*BINS + entry)*64;
    uint2 o;
    o.x = pack_h2(src[k0],   src[k0+1]);
    o.y = pack_h2(src[k0+8], src[k0+9]);
    g_cbf16h[F] = o;
}

// ---------------- k5: encoder GEMM + per-(b,e) column norms -------------------
__global__ void __launch_bounds__(256, 2) k_enc(const float* __restrict__ ew,
                                                const float* __restrict__ eb) {
    extern __shared__ float sm[];
    float* zS   = sm;               // 128*TPAD
    float* wS   = zS + 128*TPAD;    // 64*TPAD
    float* red  = wS + 64*TPAD;     // 64*17
    float* meanS= red + 64*17;      // 64
    float* sinvS= meanS + 64;       // 64
    float* ebS  = sinvS + 64;       // 64

    int tid = threadIdx.x;
    int t0 = blockIdx.x * 128;

    if (tid < 64) { meanS[tid] = g_mean[tid]; sinvS[tid] = g_sinv[tid]; ebS[tid] = eb[tid]; }
    {
        const float4* w4 = (const float4*)ew;
        #pragma unroll
        for (int i = 0; i < 4; i++) {
            int f = tid + i*256;
            int e = f >> 4, d4 = f & 15;
            float4 v = w4[f];
            float* dst = wS + e*TPAD + d4*4;
            dst[0]=v.x; dst[1]=v.y; dst[2]=v.z; dst[3]=v.w;
        }
    }
    __syncthreads();
    {
        const float4* z4 = (const float4*)g_z + (size_t)t0*16;
        #pragma unroll
        for (int i = 0; i < 8; i++) {
            int f = tid + i*256;
            int t = f >> 4, d4 = f & 15;
            float4 v = z4[f];
            int l = (t0 + t) & 63;
            float m = meanS[l], si = sinvS[l];
            float* dst = zS + t*TPAD + d4*4;
            dst[0]=(v.x-m)*si; dst[1]=(v.y-m)*si; dst[2]=(v.z-m)*si; dst[3]=(v.w-m)*si;
        }
    }
    __syncthreads();

    int ty = tid >> 4, tx = tid & 15;
    ull acc2[8][4];
    #pragma unroll
    for (int i = 0; i < 8; i++)
        #pragma unroll
        for (int j = 0; j < 4; j++) acc2[i][j] = 0ull;

    #pragma unroll 8
    for (int d = 0; d < 64; d += 2) {
        ull rv[8], cv[4];
        #pragma unroll
        for (int i = 0; i < 8; i++) rv[i] = *(const ull*)(zS + (ty*8+i)*TPAD + d);
        #pragma unroll
        for (int j = 0; j < 4; j++) cv[j] = *(const ull*)(wS + (j*16+tx)*TPAD + d);
        #pragma unroll
        for (int i = 0; i < 8; i++)
            #pragma unroll
            for (int j = 0; j < 4; j++) fma2(acc2[i][j], rv[i], cv[j]);
    }

    float pn[4] = {0.f,0.f,0.f,0.f};
    #pragma unroll
    for (int i = 0; i < 8; i++) {
        int t = t0 + ty*8 + i;
        #pragma unroll
        for (int j = 0; j < 4; j++) {
            int e = j*16 + tx;
            float o = unpack_sum(acc2[i][j]) + ebS[e];
            pn[j] += o*o;
            g_zh[(size_t)t*64 + e] = o;
        }
    }
    #pragma unroll
    for (int j = 0; j < 4; j++) red[(j*16+tx)*17 + ty] = pn[j];
    __syncthreads();
    if (tid < 64) {
        float s = 0.f;
        #pragma unroll
        for (int y = 0; y < 16; y++) s += red[tid*17 + y];
        atomicAdd(&g_colnorm[(t0 >> 10)*64 + tid], (double)s);
    }
}

// ---------------- k6: finalize inverse token-norms ----------------------------
__global__ void k_normfin() {
    int i = blockIdx.x*blockDim.x + threadIdx.x;
    if (i < BB*DD) g_invnorm[i] = 1.0f / sqrtf((float)g_colnorm[i]);
}

// ====================== k7: hi-pass mma RVQ + certified argmin =================
// 128 blocks x 256 threads (8 warps); warp owns 32 tokens = two m16 tiles.
// ONE fp16 hi*hi mma pass; per token track best-2 of m_hi; decision certified
// when bm2-bm >= 2E with E = 2^-9*1.2*||r||*||c||max + slop; else exact fp32
// warp-cooperative rescan (rare).

// smem float offsets (overlay: stage view / decode view)
#define F_BF    0                  // 2048 floats = 2048 uint2/2... (two 1024-uint2 buffers = 4096 floats)
#define F_CSQ   4096               // 1024
#define F_SCR   5120               // 512 (8 warps x 64, fallback residual)
#define F_QO    0                  // decode: 256*66 = 16896
#define F_DW    16896              // decode: 64*66 = 4224
#define F_FIX   21120
#define F_INV   (F_FIX)
#define F_MEAN  (F_FIX+64)
#define F_SPE   (F_FIX+128)
#define F_DB    (F_FIX+192)
#define F_LOSS  (F_FIX+256)        // 8
#define RVQ_SMEMF (F_FIX+272)
#define RVQ_SMEM  (RVQ_SMEMF*4)

#define UPD(sl, mval, iv) do { \
    float _m = (mval); \
    if (_m < bm[sl]) { bm2[sl] = bm[sl]; bm[sl] = _m; bi[sl] = (iv); } \
    else if (_m < bm2[sl]) bm2[sl] = _m; \
} while (0)

__global__ void __launch_bounds__(256) k_rvq(const float* __restrict__ cb,
                                             const float* __restrict__ dw,
                                             const float* __restrict__ db,
                                             float* __restrict__ out) {
    extern __shared__ float sm[];
    uint2* bf2   = (uint2*)(sm + F_BF);
    float* csqS  = sm + F_CSQ;
    float* scr   = sm + F_SCR;
    float* invS  = sm + F_INV;
    float* meanS = sm + F_MEAN;
    float* speS  = sm + F_SPE;
    float* dbS   = sm + F_DB;
    float* lossW = sm + F_LOSS;

    int tid = threadIdx.x;
    int w = tid >> 5, lane = tid & 31;
    int g = lane >> 2, tig = lane & 3;
    int t0 = blockIdx.x * 256;
    int b  = t0 >> 10;

    if (tid < 64) {
        invS[tid]  = g_invnorm[b*64 + tid];
        meanS[tid] = g_mean[tid];
        speS[tid]  = g_spe[tid];
        dbS[tid]   = db[tid];
    }
    __syncthreads();

    int mb = 32*w;
    // residual registers, A-fragment layout:
    // R[mt][s*4+j]  rows mb+16mt+g   ; R1v[mt][..] rows mb+16mt+g+8
    // k = 16s + 2tig + (j&1) + 8*(j>>1)
    float R[2][16], R1v[2][16];
    #pragma unroll
    for (int mt = 0; mt < 2; mt++) {
        const float* z0 = g_zh + (size_t)(t0 + mb + 16*mt + g)*64;
        const float* z1 = z0 + 8*64;
        #pragma unroll
        for (int s = 0; s < 4; s++) {
            int ka = 16*s + 2*tig;
            float2 a0 = *(const float2*)(z0 + ka);
            float2 b0 = *(const float2*)(z0 + ka + 8);
            float2 a1 = *(const float2*)(z1 + ka);
            float2 b1 = *(const float2*)(z1 + ka + 8);
            R[mt][s*4+0]  = a0.x * invS[ka];    R[mt][s*4+1]  = a0.y * invS[ka+1];
            R[mt][s*4+2]  = b0.x * invS[ka+8];  R[mt][s*4+3]  = b0.y * invS[ka+9];
            R1v[mt][s*4+0] = a1.x * invS[ka];   R1v[mt][s*4+1] = a1.y * invS[ka+1];
            R1v[mt][s*4+2] = b1.x * invS[ka+8]; R1v[mt][s*4+3] = b1.y * invS[ka+9];
        }
    }

    for (int q = 0; q < NQ; q++) {
        // ---- stage prologue: A hi fragments + token norms + thresholds ------
        uint32_t AH[2][4][4];
        float rn2[4] = {0.f, 0.f, 0.f, 0.f};   // slots: (mt0,r0),(mt0,r1),(mt1,r0),(mt1,r1)
        #pragma unroll
        for (int mt = 0; mt < 2; mt++)
            #pragma unroll
            for (int i = 0; i < 16; i++) {
                rn2[mt*2]     += R[mt][i]*R[mt][i];
                rn2[mt*2 + 1] += R1v[mt][i]*R1v[mt][i];
            }
        #pragma unroll
        for (int sl = 0; sl < 4; sl++) {
            rn2[sl] += __shfl_xor_sync(0xffffffffu, rn2[sl], 1);
            rn2[sl] += __shfl_xor_sync(0xffffffffu, rn2[sl], 2);
        }
        float cbnmax = sqrtf(__int_as_float(g_cbnmax_i[q]));
        float thr[4];
        #pragma unroll
        for (int sl = 0; sl < 4; sl++)
            thr[sl] = 4.8e-3f * sqrtf(rn2[sl]) * cbnmax + 1e-4f;   // 2E

        #pragma unroll
        for (int mt = 0; mt < 2; mt++)
            #pragma unroll
            for (int s = 0; s < 4; s++) {
                AH[mt][s][0] = pack_h2(R[mt][s*4+0],  R[mt][s*4+1]);
                AH[mt][s][1] = pack_h2(R1v[mt][s*4+0], R1v[mt][s*4+1]);
                AH[mt][s][2] = pack_h2(R[mt][s*4+2],  R[mt][s*4+3]);
                AH[mt][s][3] = pack_h2(R1v[mt][s*4+2], R1v[mt][s*4+3]);
            }

        __syncthreads();   // previous-stage smem consumers done
        #pragma unroll
        for (int i = 0; i < 4; i++) csqS[tid + i*256] = g_cbsq[q*BINS + tid + i*256];
        {   // prefill chunk 0 into buf 0 (1024 uint2 / 256 threads)
            const uint2* src = g_cbf16h + (size_t)(q*16 + 0)*1024;
            #pragma unroll
            for (int i = 0; i < 4; i++) bf2[tid + i*256] = src[tid + i*256];
        }
        __syncthreads();

        float bm[4]  = {INFINITY, INFINITY, INFINITY, INFINITY};
        float bm2[4] = {INFINITY, INFINITY, INFINITY, INFINITY};
        int   bi[4]  = {0, 0, 0, 0};

        for (int ch = 0; ch < 16; ch++) {
            if (ch < 15) {   // prefetch next chunk into other buffer
                const uint2* src = g_cbf16h + (size_t)(q*16 + ch + 1)*1024;
                uint2* dst = bf2 + ((ch + 1) & 1)*1024;
                #pragma unroll
                for (int i = 0; i < 4; i++) dst[tid + i*256] = src[tid + i*256];
            }
            const uint2* buf = bf2 + (ch & 1)*1024;

            float C[2][8][4];
            #pragma unroll
            for (int mt = 0; mt < 2; mt++)
                #pragma unroll
                for (int nt = 0; nt < 8; nt++)
                    #pragma unroll
                    for (int j = 0; j < 4; j++) C[mt][nt][j] = 0.f;

            #pragma unroll
            for (int s = 0; s < 4; s++) {
                #pragma unroll
                for (int nt = 0; nt < 8; nt++) {
                    uint2 bv = buf[(nt*4 + s)*32 + lane];
                    mma_f16(C[0][nt], AH[0][s], bv.x, bv.y);
                    mma_f16(C[1][nt], AH[1][s], bv.x, bv.y);
                }
            }

            // best-2 epilogue
            #pragma unroll
            for (int nt = 0; nt < 8; nt++) {
                int nb = ch*64 + nt*8 + 2*tig;
                float cq0 = csqS[nb], cq1 = csqS[nb + 1];
                UPD(0, cq0 - 2.0f*C[0][nt][0], nb);
                UPD(0, cq1 - 2.0f*C[0][nt][1], nb + 1);
                UPD(1, cq0 - 2.0f*C[0][nt][2], nb);
                UPD(1, cq1 - 2.0f*C[0][nt][3], nb + 1);
                UPD(2, cq0 - 2.0f*C[1][nt][0], nb);
                UPD(2, cq1 - 2.0f*C[1][nt][1], nb + 1);
                UPD(3, cq0 - 2.0f*C[1][nt][2], nb);
                UPD(3, cq1 - 2.0f*C[1][nt][3], nb + 1);
            }
            __syncthreads();   // all warps done with buf[ch&1] before refill
        }

        // cross-lane best-2 merge over the 4 lanes of the column group
        #pragma unroll
        for (int off = 1; off <= 2; off <<= 1) {
            #pragma unroll
            for (int sl = 0; sl < 4; sl++) {
                float ob  = __shfl_xor_sync(0xffffffffu, bm[sl], off);
                int   oi  = __shfl_xor_sync(0xffffffffu, bi[sl], off);
                float ob2 = __shfl_xor_sync(0xffffffffu, bm2[sl], off);
                if (ob < bm[sl] || (ob == bm[sl] && oi < bi[sl])) {
                    bm2[sl] = fminf(bm[sl], ob2);
                    bm[sl] = ob; bi[sl] = oi;
                } else {
                    bm2[sl] = fminf(bm2[sl], ob);
                }
            }
        }

        // ---- certification + exact fallback (rare) --------------------------
        #pragma unroll
        for (int sl = 0; sl < 4; sl++) {
            const int mt = sl >> 1, rr = sl & 1;
            bool unc = (bm2[sl] - bm[sl]) < thr[sl];
            unsigned mask = __ballot_sync(0xffffffffu, (tig == 0) && unc);
            while (mask) {
                int src = __ffs(mask) - 1; mask &= mask - 1;
                int grp = src >> 2;
                if (g == grp) {   // owner lanes dump residual to scratch
                    #pragma unroll
                    for (int s = 0; s < 4; s++) {
                        int ka = 16*s + 2*tig;
                        const float* rp = rr ? R1v[mt] : R[mt];
                        scr[w*64 + ka]     = rp[s*4+0];
                        scr[w*64 + ka + 1] = rp[s*4+1];
                        scr[w*64 + ka + 8] = rp[s*4+2];
                        scr[w*64 + ka + 9] = rp[s*4+3];
                    }
                }
                __syncwarp();
                float4 rv4[16];
                {
                    const float4* s4 = (const float4*)(scr + w*64);
                    #pragma unroll
                    for (int i = 0; i < 16; i++) rv4[i] = s4[i];
                }
                float bL = INFINITY; int iL = 0;
                const float4* cbq = (const float4*)(cb + (size_t)q*BINS*64);
                for (int e = 0; e < 32; e++) {
                    int idx = lane*32 + e;
                    const float4* cr = cbq + idx*16;
                    float dot = 0.f;
                    #pragma unroll
                    for (int kk = 0; kk < 16; kk++) {
                        float4 c4 = cr[kk];
                        dot += rv4[kk].x*c4.x + rv4[kk].y*c4.y
                             + rv4[kk].z*c4.z + rv4[kk].w*c4.w;
                    }
                    float m = csqS[idx] - 2.0f*dot;
                    if (m < bL) { bL = m; iL = idx; }
                }
                #pragma unroll
                for (int off = 16; off; off >>= 1) {
                    float ov = __shfl_xor_sync(0xffffffffu, bL, off);
                    int   oi = __shfl_xor_sync(0xffffffffu, iL, off);
                    if (ov < bL || (ov == bL && oi < iL)) { bL = ov; iL = oi; }
                }
                if (g == grp) bi[sl] = iL;
                __syncwarp();
            }
        }

        if (tig == 0) {
            float* cp = out + ZQ_OFF + q*NTOK + t0 + mb;
            cp[g]      = (float)bi[0];
            cp[g + 8]  = (float)bi[1];
            cp[g + 16] = (float)bi[2];
            cp[g + 24] = (float)bi[3];
        }

        // residual update + loss
        float ls = 0.f;
        #pragma unroll
        for (int mt = 0; mt < 2; mt++) {
            int i0 = mt ? bi[2] : bi[0];
            int i1 = mt ? bi[3] : bi[1];
            const float* cr0 = cb + ((size_t)q*BINS + i0)*64;
            const float* cr1 = cb + ((size_t)q*BINS + i1)*64;
            #pragma unroll
            for (int s = 0; s < 4; s++) {
                int ka = 16*s + 2*tig;
                float2 c0a = *(const float2*)(cr0 + ka);
                float2 c0b = *(const float2*)(cr0 + ka + 8);
                float2 c1a = *(const float2*)(cr1 + ka);
                float2 c1b = *(const float2*)(cr1 + ka + 8);
                float nv;
                nv = R[mt][s*4+0]-c0a.x;  R[mt][s*4+0]=nv;  ls += nv*nv;
                nv = R[mt][s*4+1]-c0a.y;  R[mt][s*4+1]=nv;  ls += nv*nv;
                nv = R[mt][s*4+2]-c0b.x;  R[mt][s*4+2]=nv;  ls += nv*nv;
                nv = R[mt][s*4+3]-c0b.y;  R[mt][s*4+3]=nv;  ls += nv*nv;
                nv = R1v[mt][s*4+0]-c1a.x; R1v[mt][s*4+0]=nv; ls += nv*nv;
                nv = R1v[mt][s*4+1]-c1a.y; R1v[mt][s*4+1]=nv; ls += nv*nv;
                nv = R1v[mt][s*4+2]-c1b.x; R1v[mt][s*4+2]=nv; ls += nv*nv;
                nv = R1v[mt][s*4+3]-c1b.y; R1v[mt][s*4+3]=nv; ls += nv*nv;
            }
        }
        #pragma unroll
        for (int o = 16; o; o >>= 1) ls += __shfl_xor_sync(0xffffffffu, ls, o);
        if (lane == 0) lossW[w] = ls;
        __syncthreads();
        if (tid == 0) {
            float s = 0.f;
            #pragma unroll
            for (int i = 0; i < 8; i++) s += lossW[i];
            atomicAdd(&g_loss[q], (double)s);
        }
        __syncthreads();
    }

    // -------- decode: QO = R_init - R_final; out = (QO @ dw^T + db)*spe + mean
    {
        float* qoS = sm + F_QO;
        #pragma unroll
        for (int mt = 0; mt < 2; mt++) {
            int r0l = mb + 16*mt + g, r1l = r0l + 8;
            const float* z0 = g_zh + (size_t)(t0 + r0l)*64;
            const float* z1 = g_zh + (size_t)(t0 + r1l)*64;
            #pragma unroll
            for (int s = 0; s < 4; s++) {
                int ka = 16*s + 2*tig;
                float2 a0 = *(const float2*)(z0 + ka);
                float2 b0 = *(const float2*)(z0 + ka + 8);
                float2 a1 = *(const float2*)(z1 + ka);
                float2 b1 = *(const float2*)(z1 + ka + 8);
                qoS[r0l*TPAD + ka]     = a0.x*invS[ka]   - R[mt][s*4+0];
                qoS[r0l*TPAD + ka + 1] = a0.y*invS[ka+1] - R[mt][s*4+1];
                qoS[r0l*TPAD + ka + 8] = b0.x*invS[ka+8] - R[mt][s*4+2];
                qoS[r0l*TPAD + ka + 9] = b0.y*invS[ka+9] - R[mt][s*4+3];
                qoS[r1l*TPAD + ka]     = a1.x*invS[ka]   - R1v[mt][s*4+0];
                qoS[r1l*TPAD + ka + 1] = a1.y*invS[ka+1] - R1v[mt][s*4+1];
                qoS[r1l*TPAD + ka + 8] = b1.x*invS[ka+8] - R1v[mt][s*4+2];
                qoS[r1l*TPAD + ka + 9] = b1.y*invS[ka+9] - R1v[mt][s*4+3];
            }
        }
        float* dwS = sm + F_DW;
        #pragma unroll
        for (int i = 0; i < 16; i++) {
            int f = tid + i*256;
            int e = f >> 6, k = f & 63;
            dwS[e*TPAD + k] = dw[f];
        }
        __syncthreads();

        int ty = tid >> 4, tx = tid & 15;
        #pragma unroll
        for (int half = 0; half < 2; half++) {
            float acc[8][4];
            #pragma unroll
            for (int i = 0; i < 8; i++)
                #pragma unroll
                for (int j = 0; j < 4; j++) acc[i][j] = 0.f;
            #pragma unroll 8
            for (int k = 0; k < 64; k++) {
                float rv[8], cv[4];
                #pragma unroll
                for (int i = 0; i < 8; i++)
                    rv[i] = qoS[(half*128 + ty*8 + i)*TPAD + k];
                #pragma unroll
                for (int j = 0; j < 4; j++) cv[j] = dwS[(j*16+tx)*TPAD + k];
                #pragma unroll
                for (int i = 0; i < 8; i++)
                    #pragma unroll
                    for (int j = 0; j < 4; j++) acc[i][j] += rv[i]*cv[j];
            }
            #pragma unroll
            for (int i = 0; i < 8; i++) {
                int t = t0 + half*128 + ty*8 + i;
                int l = t & 63;
                float sp = speS[l], mm = meanS[l];
                #pragma unroll
                for (int j = 0; j < 4; j++) {
                    int e = j*16 + tx;
                    out[(size_t)t*64 + e] = (acc[i][j] + dbS[e])*sp + mm;
                }
            }
        }
    }
}

// ---------------- k8: commit loss ---------------------------------------------
__global__ void k_lossfin(float* __restrict__ out) {
    if (threadIdx.x == 0 && blockIdx.x == 0) {
        double s = 0.0;
        for (int q = 0; q < NQ; q++) s += g_loss[q] / (double)(NTOK*DD);
        out[ZQ_OFF + CODES_N] = (float)(s / (double)NQ);
    }
}

// ---------------- launch ------------------------------------------------------
extern "C" void kernel_launch(void* const* d_in, const int* in_sizes, int n_in,
                              void* d_out, int out_size) {
    const float* x    = (const float*)d_in[0];
    const float* ew   = (const float*)d_in[1];
    const float* eb   = (const float*)d_in[2];
    const float* dwp  = (const float*)d_in[3];
    const float* dbp  = (const float*)d_in[4];
    const float* cb   = (const float*)d_in[5];
    float* out = (float*)d_out;

    const int ENC_SMEM = (128*TPAD + 64*TPAD + 64*17 + 3*64) * 4;
    cudaFuncSetAttribute(k_enc, cudaFuncAttributeMaxDynamicSharedMemorySize, ENC_SMEM);
    cudaFuncSetAttribute(k_rvq, cudaFuncAttributeMaxDynamicSharedMemorySize, RVQ_SMEM);

    k_zero<<<1, 256>>>();
    k_fft<<<BB*LL, 1024>>>(x);
    k_stats<<<512, 256>>>();
    k_statfin<<<1, 64>>>();
    k_cbsq<<<128, 256>>>(cb);
    k_cbfrag<<<(NQ*16*8*4*32 + 255)/256, 256>>>(cb);
    k_enc<<<256, 256, ENC_SMEM>>>(ew, eb);
    k_normfin<<<8, 256>>>();
    k_rvq<<<128, 256, RVQ_SMEM>>>(cb, dwp, dbp, out);
    k_lossfin<<<1, 32>>>(out);
}

// round 14
// speedup vs baseline: 2.2381x; 2.2381x over previous
#include <cuda_runtime.h>
#include <cuda_fp16.h>
#include <math.h>
#include <stdint.h>

#define BB 32
#define VV 16
#define LL 64
#define PP 64
#define DD 64
#define NTOK 32768      // BB*VV*LL
#define NQ 8
#define BINS 1024
#define EPSF 1e-5f
#define TPAD 66

#define ZQ_OFF   (NTOK*DD)           // 2097152
#define CODES_N  (NQ*NTOK)           // 262144

typedef unsigned long long ull;

// m16n8k16 f16 mma, fp32 accum (sm_80+; legal under compute_100)
__device__ __forceinline__ void mma_f16(float* c, const uint32_t* a,
                                        uint32_t b0, uint32_t b1) {
    asm volatile("mma.sync.aligned.m16n8k16.row.col.f32.f16.f16.f32 "
        "{%0,%1,%2,%3}, {%4,%5,%6,%7}, {%8,%9}, {%0,%1,%2,%3};"
        : "+f"(c[0]), "+f"(c[1]), "+f"(c[2]), "+f"(c[3])
        : "r"(a[0]), "r"(a[1]), "r"(a[2]), "r"(a[3]), "r"(b0), "r"(b1));
}

__device__ __forceinline__ uint32_t pack_h2(float x, float y) {
    __half2 h = __floats2half2_rn(x, y);
    return *reinterpret_cast<uint32_t*>(&h);
}

// fp32x2 helpers for k_enc (lowered to 2x FFMA on sm_100; harmless)
__device__ __forceinline__ void fma2(ull& acc, ull a, ull b) {
    asm("fma.rn.f32x2 %0, %1, %2, %0;" : "+l"(acc) : "l"(a), "l"(b));
}
__device__ __forceinline__ float unpack_sum(ull a) {
    float2 p = *reinterpret_cast<float2*>(&a);
    return p.x + p.y;
}

// ---------------- scratch (device globals; no allocation allowed) -------------
__device__ __align__(16) float  g_z[NTOK*DD];
__device__ __align__(16) float  g_zh[NTOK*DD];
// fp16 hi/lo fragment codebook: F = (((q*16+ch)*8+nt)*4+s)*32+lane
// uint4 = {bhi0, bhi1, blo0, blo1}
__device__ __align__(16) uint4  g_cbf16[NQ*16*8*4*32];   // 131072 uint4
__device__ float    g_cbsq[NQ*BINS];
__device__ double   g_sum[LL], g_sumsq[LL];
__device__ double   g_colnorm[BB*DD];
__device__ double   g_loss[NQ];
__device__ unsigned g_done;

// ---------------- k_prep: codebook norms + fp16 fragments + zeroing -----------
// grid 512 x 256. cbfrag over all blocks; cbsq on blocks 0..127; zero colnorm
// on blocks 0..7; zero stats/loss/done on block 0.
__global__ void k_prep(const float* __restrict__ cb) {
    int tid = threadIdx.x;
    int F = blockIdx.x*256 + tid;
    {   // fp16 hi/lo fragment
        int lane = F & 31;
        int s    = (F >> 5) & 3;
        int nt   = (F >> 7) & 7;
        int ch   = (F >> 10) & 15;
        int q    = F >> 14;
        int g    = lane >> 2, tig = lane & 3;
        int entry = ch*64 + nt*8 + g;
        int k0 = 16*s + 2*tig;
        const float* src = cb + ((size_t)q*BINS + entry)*64;
        float v0 = src[k0],     v1 = src[k0+1];
        float v2 = src[k0+8],   v3 = src[k0+9];
        float h0 = __half2float(__float2half_rn(v0));
        float h1 = __half2float(__float2half_rn(v1));
        float h2 = __half2float(__float2half_rn(v2));
        float h3 = __half2float(__float2half_rn(v3));
        uint4 o;
        o.x = pack_h2(h0, h1);
        o.y = pack_h2(h2, h3);
        o.z = pack_h2(v0 - h0, v1 - h1);
        o.w = pack_h2(v2 - h2, v3 - h3);
        g_cbf16[F] = o;
    }
    if (blockIdx.x < 128) {   // squared norms, 64 rows/block, 4 thr/row
        int row = blockIdx.x*64 + (tid >> 2);
        const float* p = cb + (size_t)row*64 + (tid & 3)*16;
        float s = 0.f;
        #pragma unroll
        for (int i = 0; i < 16; i++) { float v = p[i]; s += v*v; }
        s += __shfl_xor_sync(0xffffffffu, s, 1);
        s += __shfl_xor_sync(0xffffffffu, s, 2);
        if ((tid & 3) == 0) g_cbsq[row] = s;
    }
    if (blockIdx.x < 8) g_colnorm[blockIdx.x*256 + tid] = 0.0;
    if (blockIdx.x == 0) {
        if (tid < LL) { g_sum[tid] = 0.0; g_sumsq[tid] = 0.0; }
        if (tid < NQ) g_loss[tid] = 0.0;
        if (tid == 0) g_done = 0u;
    }
}

// ---------------- k_fft: 64-pt DFT magnitude + fused per-l stats --------------
// grid = BB*LL blocks, 1024 threads. Real-input symmetry: compute bins 0..32
// (threads 0..527, v=i/33, kk=i%33), mirror the rest. Then block-reduce
// sum/sumsq (all 1024 mags share the same l) into double atomics.
__global__ void __launch_bounds__(1024) k_fft(const float* __restrict__ x) {
    __shared__ float xs[PP*VV];
    __shared__ float ct[64], st[64];
    __shared__ float mags[VV*33];
    __shared__ float redp[64];
    int bi = blockIdx.x;
    int b = bi >> 6, l = bi & 63;
    int tid = threadIdx.x;
    xs[tid] = x[(size_t)(b*4096 + l*64)*16 + tid];
    if (tid < 64) { float a = (float)tid * (1.0f/32.0f); ct[tid] = cospif(a); st[tid] = sinpif(a); }
    __syncthreads();
    if (tid < 528) {
        int v = tid / 33, kk = tid % 33;
        float re = 0.f, im = 0.f;
        #pragma unroll 16
        for (int j = 0; j < 64; j++) {
            float val = xs[j*16 + v];
            int a = (j*kk) & 63;
            re += val * ct[a];
            im += val * st[a];
        }
        mags[v*33 + kk] = sqrtf(re*re + im*im);
    }
    __syncthreads();
    int v = tid >> 6, k = tid & 63;
    int kk = (k <= 32) ? k : (64 - k);
    float mag = mags[v*33 + kk];
    int t = (b*VV + v)*LL + l;
    g_z[t*64 + k] = mag;
    // fused stats (whole block shares l)
    float s = mag, ss = mag*mag;
    #pragma unroll
    for (int o = 16; o; o >>= 1) {
        s  += __shfl_xor_sync(0xffffffffu, s, o);
        ss += __shfl_xor_sync(0xffffffffu, ss, o);
    }
    int wid = tid >> 5, lane = tid & 31;
    if (lane == 0) { redp[wid] = s; redp[32 + wid] = ss; }
    __syncthreads();
    if (tid < 32) {
        float s2 = redp[tid], ss2 = redp[32 + tid];
        #pragma unroll
        for (int o = 16; o; o >>= 1) {
            s2  += __shfl_xor_sync(0xffffffffu, s2, o);
            ss2 += __shfl_xor_sync(0xffffffffu, ss2, o);
        }
        if (tid == 0) {
            atomicAdd(&g_sum[l], (double)s2);
            atomicAdd(&g_sumsq[l], (double)ss2);
        }
    }
}

// helper: per-l mean / (std+eps) from accumulated double sums (ddof=1)
__device__ __forceinline__ void stat_ml(int l, float& mean_out, float& spe_out) {
    double n = 32768.0;
    double s = g_sum[l], ss = g_sumsq[l];
    double mean = s / n;
    double var = (ss - s*s/n) / (n - 1.0);
    mean_out = (float)mean;
    spe_out = (float)sqrt(var) + EPSF;
}

// ---------------- k_enc: encoder GEMM + per-(b,e) column norms ----------------
__global__ void __launch_bounds__(256, 2) k_enc(const float* __restrict__ ew,
                                                const float* __restrict__ eb) {
    extern __shared__ float sm[];
    float* zS   = sm;               // 128*TPAD
    float* wS   = zS + 128*TPAD;    // 64*TPAD
    float* red  = wS + 64*TPAD;     // 64*17
    float* meanS= red + 64*17;      // 64
    float* sinvS= meanS + 64;       // 64
    float* ebS  = sinvS + 64;       // 64

    int tid = threadIdx.x;
    int t0 = blockIdx.x * 128;

    if (tid < 64) {
        float mn, sp; stat_ml(tid, mn, sp);
        meanS[tid] = mn; sinvS[tid] = 1.0f / sp; ebS[tid] = eb[tid];
    }
    {
        const float4* w4 = (const float4*)ew;
        #pragma unroll
        for (int i = 0; i < 4; i++) {
            int f = tid + i*256;
            int e = f >> 4, d4 = f & 15;
            float4 v = w4[f];
            float* dst = wS + e*TPAD + d4*4;
            dst[0]=v.x; dst[1]=v.y; dst[2]=v.z; dst[3]=v.w;
        }
    }
    __syncthreads();
    {
        const float4* z4 = (const float4*)g_z + (size_t)t0*16;
        #pragma unroll
        for (int i = 0; i < 8; i++) {
            int f = tid + i*256;
            int t = f >> 4, d4 = f & 15;
            float4 v = z4[f];
            int l = (t0 + t) & 63;
            float m = meanS[l], si = sinvS[l];
            float* dst = zS + t*TPAD + d4*4;
            dst[0]=(v.x-m)*si; dst[1]=(v.y-m)*si; dst[2]=(v.z-m)*si; dst[3]=(v.w-m)*si;
        }
    }
    __syncthreads();

    int ty = tid >> 4, tx = tid & 15;
    ull acc2[8][4];
    #pragma unroll
    for (int i = 0; i < 8; i++)
        #pragma unroll
        for (int j = 0; j < 4; j++) acc2[i][j] = 0ull;

    #pragma unroll 8
    for (int d = 0; d < 64; d += 2) {
        ull rv[8], cv[4];
        #pragma unroll
        for (int i = 0; i < 8; i++) rv[i] = *(const ull*)(zS + (ty*8+i)*TPAD + d);
        #pragma unroll
        for (int j = 0; j < 4; j++) cv[j] = *(const ull*)(wS + (j*16+tx)*TPAD + d);
        #pragma unroll
        for (int i = 0; i < 8; i++)
            #pragma unroll
            for (int j = 0; j < 4; j++) fma2(acc2[i][j], rv[i], cv[j]);
    }

    float pn[4] = {0.f,0.f,0.f,0.f};
    #pragma unroll
    for (int i = 0; i < 8; i++) {
        int t = t0 + ty*8 + i;
        #pragma unroll
        for (int j = 0; j < 4; j++) {
            int e = j*16 + tx;
            float o = unpack_sum(acc2[i][j]) + ebS[e];
            pn[j] += o*o;
            g_zh[(size_t)t*64 + e] = o;
        }
    }
    #pragma unroll
    for (int j = 0; j < 4; j++) red[(j*16+tx)*17 + ty] = pn[j];
    __syncthreads();
    if (tid < 64) {
        float s = 0.f;
        #pragma unroll
        for (int y = 0; y < 16; y++) s += red[tid*17 + y];
        atomicAdd(&g_colnorm[(t0 >> 10)*64 + tid], (double)s);
    }
}

// ============================ k_rvq: fp16x3 mma RVQ ============================
// 128 blocks x 512 threads (16 warps); warp w owns token rows 16w..16w+15.
// Residual in registers (m16n8k16 A-fragment layout). QO = R_init - R_final,
// recomputed at decode time. Inline: invnorm, mean/spe; last block writes loss.

// smem float offsets (overlay: stage view / decode view)
#define F_BF    0                  // 8192 floats = 2048 uint4 (two chunk buffers)
#define F_CSQ   8448               // 1024
#define F_QO    0                  // decode: 256*66 = 16896
#define F_DW    16896              // decode: 64*66 = 4224
#define F_FIX   21120
#define F_INV   (F_FIX)
#define F_MEAN  (F_FIX+64)
#define F_SPE   (F_FIX+128)
#define F_DB    (F_FIX+192)
#define F_LOSS  (F_FIX+256)        // 16
#define RVQ_SMEMF (F_FIX+272)
#define RVQ_SMEM  (RVQ_SMEMF*4)

__global__ void __launch_bounds__(512) k_rvq(const float* __restrict__ cb,
                                             const float* __restrict__ dw,
                                             const float* __restrict__ db,
                                             float* __restrict__ out) {
    extern __shared__ float sm[];
    uint4* bf4   = (uint4*)(sm + F_BF);
    float* csqS  = sm + F_CSQ;
    float* invS  = sm + F_INV;
    float* meanS = sm + F_MEAN;
    float* speS  = sm + F_SPE;
    float* dbS   = sm + F_DB;
    float* lossW = sm + F_LOSS;

    int tid = threadIdx.x;
    int w = tid >> 5, lane = tid & 31;
    int g = lane >> 2, tig = lane & 3;
    int t0 = blockIdx.x * 256;
    int b  = t0 >> 10;

    if (tid < 64) {
        invS[tid] = 1.0f / sqrtf((float)g_colnorm[b*64 + tid]);
        float mn, sp; stat_ml(tid, mn, sp);
        meanS[tid] = mn; speS[tid] = sp;
        dbS[tid]   = db[tid];
    }
    __syncthreads();

    int m0l = 16*w + g, m1l = m0l + 8;
    int m0g = t0 + m0l, m1g = t0 + m1l;

    // residual registers in A-fragment layout:
    // R[s*4+j]: k = 16s + 2tig + (j&1) + 8*(j>>1)
    float R0[16], R1[16];
    {
        const float* z0 = g_zh + (size_t)m0g*64;
        const float* z1 = g_zh + (size_t)m1g*64;
        #pragma unroll
        for (int s = 0; s < 4; s++) {
            int ka = 16*s + 2*tig;
            float2 a0 = *(const float2*)(z0 + ka);
            float2 b0 = *(const float2*)(z0 + ka + 8);
            float2 a1 = *(const float2*)(z1 + ka);
            float2 b1 = *(const float2*)(z1 + ka + 8);
            R0[s*4+0] = a0.x * invS[ka];     R0[s*4+1] = a0.y * invS[ka+1];
            R0[s*4+2] = b0.x * invS[ka+8];   R0[s*4+3] = b0.y * invS[ka+9];
            R1[s*4+0] = a1.x * invS[ka];     R1[s*4+1] = a1.y * invS[ka+1];
            R1[s*4+2] = b1.x * invS[ka+8];   R1[s*4+3] = b1.y * invS[ka+9];
        }
    }

    for (int q = 0; q < NQ; q++) {
        // A hi/lo fragments for this stage
        uint32_t AH[4][4], AL[4][4];
        #pragma unroll
        for (int s = 0; s < 4; s++) {
            float h00 = __half2float(__float2half_rn(R0[s*4+0]));
            float h01 = __half2float(__float2half_rn(R0[s*4+1]));
            float h02 = __half2float(__float2half_rn(R0[s*4+2]));
            float h03 = __half2float(__float2half_rn(R0[s*4+3]));
            float h10 = __half2float(__float2half_rn(R1[s*4+0]));
            float h11 = __half2float(__float2half_rn(R1[s*4+1]));
            float h12 = __half2float(__float2half_rn(R1[s*4+2]));
            float h13 = __half2float(__float2half_rn(R1[s*4+3]));
            AH[s][0] = pack_h2(h00, h01);
            AH[s][1] = pack_h2(h10, h11);
            AH[s][2] = pack_h2(h02, h03);
            AH[s][3] = pack_h2(h12, h13);
            AL[s][0] = pack_h2(R0[s*4+0]-h00, R0[s*4+1]-h01);
            AL[s][1] = pack_h2(R1[s*4+0]-h10, R1[s*4+1]-h11);
            AL[s][2] = pack_h2(R0[s*4+2]-h02, R0[s*4+3]-h03);
            AL[s][3] = pack_h2(R1[s*4+2]-h12, R1[s*4+3]-h13);
        }

        __syncthreads();   // previous-iteration smem consumers done
        csqS[tid]       = g_cbsq[q*BINS + tid];
        csqS[tid + 512] = g_cbsq[q*BINS + tid + 512];
        // prefill chunk 0 into buf 0 (1024 uint4 / 512 threads)
        {
            const uint4* src = g_cbf16 + (size_t)(q*16 + 0)*1024;
            bf4[tid]       = src[tid];
            bf4[tid + 512] = src[tid + 512];
        }
        __syncthreads();

        float best0 = INFINITY, best1 = INFINITY;
        int idx0 = 0, idx1 = 0;

        for (int ch = 0; ch < 16; ch++) {
            if (ch < 15) {   // prefetch next chunk into other buffer
                const uint4* src = g_cbf16 + (size_t)(q*16 + ch + 1)*1024;
                uint4* dst = bf4 + ((ch + 1) & 1)*1024;
                dst[tid]       = src[tid];
                dst[tid + 512] = src[tid + 512];
            }
            const uint4* buf = bf4 + (ch & 1)*1024;

            float C[8][4];
            #pragma unroll
            for (int nt = 0; nt < 8; nt++)
                #pragma unroll
                for (int j = 0; j < 4; j++) C[nt][j] = 0.f;

            #pragma unroll
            for (int s = 0; s < 4; s++) {
                #pragma unroll
                for (int nt = 0; nt < 8; nt++) {
                    uint4 bv = buf[(nt*4 + s)*32 + lane];
                    mma_f16(C[nt], AH[s], bv.x, bv.y);   // hi*hi
                    mma_f16(C[nt], AL[s], bv.x, bv.y);   // lo*hi
                    mma_f16(C[nt], AH[s], bv.z, bv.w);   // hi*lo
                }
            }

            // argmin epilogue: C cols 2tig, 2tig+1
            #pragma unroll
            for (int nt = 0; nt < 8; nt++) {
                int nb = ch*64 + nt*8 + 2*tig;
                float cq0 = csqS[nb], cq1 = csqS[nb + 1];
                float m00 = cq0 - 2.0f*C[nt][0];
                float m01 = cq1 - 2.0f*C[nt][1];
                float m10 = cq0 - 2.0f*C[nt][2];
                float m11 = cq1 - 2.0f*C[nt][3];
                if (m00 < best0) { best0 = m00; idx0 = nb; }
                if (m01 < best0) { best0 = m01; idx0 = nb + 1; }
                if (m10 < best1) { best1 = m10; idx1 = nb; }
                if (m11 < best1) { best1 = m11; idx1 = nb + 1; }
            }
            __syncthreads();   // all warps done with buf[ch&1] before refill
        }

        // cross-lane argmin over the 4 lanes of the column group
        #pragma unroll
        for (int off = 1; off <= 2; off <<= 1) {
            float ov = __shfl_xor_sync(0xffffffffu, best0, off);
            int   oi = __shfl_xor_sync(0xffffffffu, idx0, off);
            if (ov < best0 || (ov == best0 && oi < idx0)) { best0 = ov; idx0 = oi; }
            ov = __shfl_xor_sync(0xffffffffu, best1, off);
            oi = __shfl_xor_sync(0xffffffffu, idx1, off);
            if (ov < best1 || (ov == best1 && oi < idx1)) { best1 = ov; idx1 = oi; }
        }
        if (tig == 0) {
            out[ZQ_OFF + q*NTOK + m0g] = (float)idx0;
            out[ZQ_OFF + q*NTOK + m1g] = (float)idx1;
        }

        // residual update + loss
        float ls = 0.f;
        {
            const float* cr0 = cb + ((size_t)q*BINS + idx0)*64;
            const float* cr1 = cb + ((size_t)q*BINS + idx1)*64;
            #pragma unroll
            for (int s = 0; s < 4; s++) {
                int ka = 16*s + 2*tig;
                float2 c0a = *(const float2*)(cr0 + ka);
                float2 c0b = *(const float2*)(cr0 + ka + 8);
                float2 c1a = *(const float2*)(cr1 + ka);
                float2 c1b = *(const float2*)(cr1 + ka + 8);
                float nv;
                nv = R0[s*4+0]-c0a.x; R0[s*4+0]=nv; ls += nv*nv;
                nv = R0[s*4+1]-c0a.y; R0[s*4+1]=nv; ls += nv*nv;
                nv = R0[s*4+2]-c0b.x; R0[s*4+2]=nv; ls += nv*nv;
                nv = R0[s*4+3]-c0b.y; R0[s*4+3]=nv; ls += nv*nv;
                nv = R1[s*4+0]-c1a.x; R1[s*4+0]=nv; ls += nv*nv;
                nv = R1[s*4+1]-c1a.y; R1[s*4+1]=nv; ls += nv*nv;
                nv = R1[s*4+2]-c1b.x; R1[s*4+2]=nv; ls += nv*nv;
                nv = R1[s*4+3]-c1b.y; R1[s*4+3]=nv; ls += nv*nv;
            }
        }
        #pragma unroll
        for (int o = 16; o; o >>= 1) ls += __shfl_xor_sync(0xffffffffu, ls, o);
        if (lane == 0) lossW[w] = ls;
        __syncthreads();
        if (tid == 0) {
            float s = 0.f;
            #pragma unroll
            for (int i = 0; i < 16; i++) s += lossW[i];
            atomicAdd(&g_loss[q], (double)s);
        }
        __syncthreads();
    }

    // -------- decode: QO = R_init - R_final; out = (QO @ dw^T + db)*spe + mean
    {
        float* qoS = sm + F_QO;
        // scatter QO fragments to smem (recompute R_init from g_zh)
        const float* z0 = g_zh + (size_t)m0g*64;
        const float* z1 = g_zh + (size_t)m1g*64;
        #pragma unroll
        for (int s = 0; s < 4; s++) {
            int ka = 16*s + 2*tig;
            float2 a0 = *(const float2*)(z0 + ka);
            float2 b0 = *(const float2*)(z0 + ka + 8);
            float2 a1 = *(const float2*)(z1 + ka);
            float2 b1 = *(const float2*)(z1 + ka + 8);
            qoS[m0l*TPAD + ka]     = a0.x*invS[ka]   - R0[s*4+0];
            qoS[m0l*TPAD + ka + 1] = a0.y*invS[ka+1] - R0[s*4+1];
            qoS[m0l*TPAD + ka + 8] = b0.x*invS[ka+8] - R0[s*4+2];
            qoS[m0l*TPAD + ka + 9] = b0.y*invS[ka+9] - R0[s*4+3];
            qoS[m1l*TPAD + ka]     = a1.x*invS[ka]   - R1[s*4+0];
            qoS[m1l*TPAD + ka + 1] = a1.y*invS[ka+1] - R1[s*4+1];
            qoS[m1l*TPAD + ka + 8] = b1.x*invS[ka+8] - R1[s*4+2];
            qoS[m1l*TPAD + ka + 9] = b1.y*invS[ka+9] - R1[s*4+3];
        }
        float* dwS = sm + F_DW;
        #pragma unroll
        for (int i = 0; i < 8; i++) {
            int f = tid + i*512;
            int e = f >> 6, k = f & 63;
            dwS[e*TPAD + k] = dw[f];
        }
        __syncthreads();

        int ty = tid >> 4, tx = tid & 15;   // 32 token-groups x 16 e-lanes
        float acc[8][4];
        #pragma unroll
        for (int i = 0; i < 8; i++)
            #pragma unroll
            for (int j = 0; j < 4; j++) acc[i][j] = 0.f;
        #pragma unroll 8
        for (int k = 0; k < 64; k++) {
            float rv[8], cv[4];
            #pragma unroll
            for (int i = 0; i < 8; i++) rv[i] = qoS[(ty*8+i)*TPAD + k];
            #pragma unroll
            for (int j = 0; j < 4; j++) cv[j] = dwS[(j*16+tx)*TPAD + k];
            #pragma unroll
            for (int i = 0; i < 8; i++)
                #pragma unroll
                for (int j = 0; j < 4; j++) acc[i][j] += rv[i]*cv[j];
        }
        #pragma unroll
        for (int i = 0; i < 8; i++) {
            int t = t0 + ty*8 + i;
            int l = t & 63;
            float sp = speS[l], mm = meanS[l];
            #pragma unroll
            for (int j = 0; j < 4; j++) {
                int e = j*16 + tx;
                out[(size_t)t*64 + e] = (acc[i][j] + dbS[e])*sp + mm;
            }
        }
    }

    // -------- commit loss: last block to finish writes the scalar -------------
    __syncthreads();
    if (tid == 0) {
        __threadfence();
        unsigned done = atomicAdd(&g_done, 1u);
        if (done == 127u) {
            double s = 0.0;
            #pragma unroll
            for (int q = 0; q < NQ; q++) s += g_loss[q] / (double)(NTOK*DD);
            out[ZQ_OFF + CODES_N] = (float)(s / (double)NQ);
        }
    }
}

// ---------------- launch ------------------------------------------------------
extern "C" void kernel_launch(void* const* d_in, const int* in_sizes, int n_in,
                              void* d_out, int out_size) {
    const float* x    = (const float*)d_in[0];
    const float* ew   = (const float*)d_in[1];
    const float* eb   = (const float*)d_in[2];
    const float* dwp  = (const float*)d_in[3];
    const float* dbp  = (const float*)d_in[4];
    const float* cb   = (const float*)d_in[5];
    float* out = (float*)d_out;

    const int ENC_SMEM = (128*TPAD + 64*TPAD + 64*17 + 3*64) * 4;
    cudaFuncSetAttribute(k_enc, cudaFuncAttributeMaxDynamicSharedMemorySize, ENC_SMEM);
    cudaFuncSetAttribute(k_rvq, cudaFuncAttributeMaxDynamicSharedMemorySize, RVQ_SMEM);

    k_prep<<<512, 256>>>(cb);
    k_fft<<<BB*LL, 1024>>>(x);
    k_enc<<<256, 256, ENC_SMEM>>>(ew, eb);
    k_rvq<<<128, 512, RVQ_SMEM>>>(cb, dwp, dbp, out);
}